// round 1
// baseline (speedup 1.0000x reference)
#include <cuda_runtime.h>

#define Bb 32
#define Tt 256
#define Ee 256
#define Hh 512
#define Gg 2048
#define Kk 32
#define NEGV -10000.0f
#define NRNN_CTAS 128

// ---------------- scratch (static device allocations only) ----------------
__device__ float g_xw[2][Tt][Bb][Gg];       // 128 MB: precomputed x@W_ih + b, bwd time-flipped
__device__ float g_hall[2][Tt][Bb][Hh];     // 32 MB: all hidden states (bwd un-flipped)
__device__ float g_hbuf[2][2][Bb][Hh];      // double-buffered current h [parity][dir][b][k]
__device__ float g_feats[Tt][Bb][Kk];       // 1 MB
__device__ unsigned g_bar_cnt;

// ---------------- helpers ----------------
__device__ __forceinline__ float sigf(float x) { return 1.0f / (1.0f + __expf(-x)); }
__device__ __forceinline__ float tanhfast(float x) { return 1.0f - 2.0f / (1.0f + __expf(2.0f * x)); }

__device__ __forceinline__ void grid_barrier(unsigned target) {
    __syncthreads();
    if (threadIdx.x == 0) {
        __threadfence();
        atomicAdd(&g_bar_cnt, 1u);
        while (*((volatile unsigned*)&g_bar_cnt) < target) { }
        __threadfence();
    }
    __syncthreads();
}

// ---------------- K0: init hbuf from h0, reset barrier ----------------
__global__ void k_init(const float* __restrict__ h0) {
    int i = blockIdx.x * 256 + threadIdx.x;   // 128*256 = 32768 = 2*32*512
    ((float*)g_hbuf)[i] = h0[i];              // parity 0 buffer is first 32768 elems
    if (i == 0) g_bar_cnt = 0;
}

// ---------------- K1: xw = emb[sent] @ W_ih^T + b, both dirs ----------------
// grid (128, 32, 2), block 256. Tile 64(M) x 64(N), K-chunks of 16, 4x4/thread.
__global__ __launch_bounds__(256) void k_xw(const int* __restrict__ sent,
                                            const float* __restrict__ emb,
                                            const float* __restrict__ Wf,
                                            const float* __restrict__ bf,
                                            const float* __restrict__ Wb,
                                            const float* __restrict__ bb) {
    __shared__ float As[16][64];
    __shared__ float Bs[16][64];
    __shared__ int tok[64];
    __shared__ float bias_sh[64];

    const int tid = threadIdx.x;
    const int m0 = blockIdx.x * 64;
    const int g0 = blockIdx.y * 64;
    const int dir = blockIdx.z;
    const float* W = dir ? Wb : Wf;
    const float* bias = dir ? bb : bf;

    if (tid < 64) {
        int m = m0 + tid;
        int t = m >> 5, b = m & 31;
        tok[tid] = sent[b * Tt + t];
        bias_sh[tid] = bias[g0 + tid];
    }
    __syncthreads();

    float acc[4][4];
#pragma unroll
    for (int i = 0; i < 4; i++)
#pragma unroll
        for (int j = 0; j < 4; j++) acc[i][j] = 0.0f;

    const int mr = tid >> 2;            // 0..63 (row of A tile / row of B tile)
    const int kq = (tid & 3) * 4;       // 0,4,8,12
    const int ty = tid >> 4;            // 0..15 -> m sub-tile
    const int tx = tid & 15;            // 0..15 -> n sub-tile

    for (int kc = 0; kc < Ee; kc += 16) {
        float4 av = *(const float4*)&emb[tok[mr] * Ee + kc + kq];
        float4 bv = *(const float4*)&W[(g0 + mr) * Ee + kc + kq];
        As[kq + 0][mr] = av.x; As[kq + 1][mr] = av.y;
        As[kq + 2][mr] = av.z; As[kq + 3][mr] = av.w;
        Bs[kq + 0][mr] = bv.x; Bs[kq + 1][mr] = bv.y;
        Bs[kq + 2][mr] = bv.z; Bs[kq + 3][mr] = bv.w;
        __syncthreads();
#pragma unroll
        for (int kk = 0; kk < 16; kk++) {
            float a_[4], b_[4];
            *(float4*)a_ = *(const float4*)&As[kk][ty * 4];
            *(float4*)b_ = *(const float4*)&Bs[kk][tx * 4];
#pragma unroll
            for (int i = 0; i < 4; i++)
#pragma unroll
                for (int j = 0; j < 4; j++) acc[i][j] += a_[i] * b_[j];
        }
        __syncthreads();
    }

#pragma unroll
    for (int i = 0; i < 4; i++) {
        int m = m0 + ty * 4 + i;
        int t = m >> 5, b = m & 31;
        int tt = dir ? (Tt - 1 - t) : t;
        float4 o;
        o.x = acc[i][0] + bias_sh[tx * 4 + 0];
        o.y = acc[i][1] + bias_sh[tx * 4 + 1];
        o.z = acc[i][2] + bias_sh[tx * 4 + 2];
        o.w = acc[i][3] + bias_sh[tx * 4 + 3];
        *(float4*)&g_xw[dir][tt][b][g0 + tx * 4] = o;
    }
}

// ---------------- K2: persistent recurrent LSTM (both dirs) ----------------
// 128 CTAs x 256 thr. dir = cta>>6, each CTA owns 8 hidden units (all 4 gates).
// W_hh slice (32 rows x 512) resident in smem. Per step: h bcast via L2,
// 4-way k-split partial dots, deterministic smem reduction, gates, grid barrier.
#define WPAD 516
#define HPAD 33
#define SM_RNN_FLOATS (32 * WPAD + Hh * HPAD + 4 * 32 * 33 + 256)

__global__ __launch_bounds__(256, 1) void k_rnn(const float* __restrict__ Whf,
                                                const float* __restrict__ Whb,
                                                const float* __restrict__ c0) {
    extern __shared__ float sm[];
    float* w_sh = sm;                        // [32][516]
    float* h_sh = sm + 32 * WPAD;            // [512][33]
    float* zp   = h_sh + Hh * HPAD;          // [4][32][33] k-split partials
    float* c_sh = zp + 4 * 32 * 33;          // [8][32]

    const int tid = threadIdx.x;
    const int dir = blockIdx.x >> 6;
    const int jblock = (blockIdx.x & 63) << 3;
    const float* Wh = dir ? Whb : Whf;

    // load weight slice: local row r -> global gate row (r>>3)*512 + jblock + (r&7)
    for (int i = tid; i < 32 * 512; i += 256) {
        int r = i >> 9, k = i & 511;
        int grow = ((r >> 3) << 9) + jblock + (r & 7);
        w_sh[r * WPAD + k] = Wh[grow * Hh + k];
    }
    // cell state init
    {
        int b = tid >> 3, jj = tid & 7;
        c_sh[jj * 32 + b] = c0[(dir * Bb + b) * Hh + jblock + jj];
    }

    const int ks = tid >> 6;          // k-split group 0..3
    const int gt = tid & 63;
    const int rt = (gt >> 3) << 2;    // row base 0..28
    const int bt = (gt & 7) << 2;     // batch base 0..28
    const int k0 = ks << 7;           // k range [k0, k0+128)
    const int gb = tid >> 3;          // gate-stage batch
    const int gj = tid & 7;           // gate-stage hidden unit (local)
    __syncthreads();

    for (int t = 0; t < Tt; t++) {
        // load h (transposed into smem, conflict-free) + prefetch xw for gate stage
        const float* hb = &g_hbuf[t & 1][dir][0][0];
        for (int i4 = tid; i4 < 4096; i4 += 256) {
            int b = i4 >> 7, k4 = (i4 & 127) << 2;
            float4 v = *(const float4*)&hb[b * Hh + k4];
            h_sh[(k4 + 0) * HPAD + b] = v.x;
            h_sh[(k4 + 1) * HPAD + b] = v.y;
            h_sh[(k4 + 2) * HPAD + b] = v.z;
            h_sh[(k4 + 3) * HPAD + b] = v.w;
        }
        float xwv[4];
#pragma unroll
        for (int g4 = 0; g4 < 4; g4++)
            xwv[g4] = g_xw[dir][t][gb][(g4 << 9) + jblock + gj];
        __syncthreads();

        // partial GEMM: rows rt..rt+3, batches bt..bt+3, k in [k0, k0+128)
        float C[4][4];
#pragma unroll
        for (int i = 0; i < 4; i++)
#pragma unroll
            for (int j = 0; j < 4; j++) C[i][j] = 0.0f;

        for (int k = k0; k < k0 + 128; k += 4) {
            float w0[4], w1[4], w2[4], w3[4];
            *(float4*)w0 = *(const float4*)&w_sh[(rt + 0) * WPAD + k];
            *(float4*)w1 = *(const float4*)&w_sh[(rt + 1) * WPAD + k];
            *(float4*)w2 = *(const float4*)&w_sh[(rt + 2) * WPAD + k];
            *(float4*)w3 = *(const float4*)&w_sh[(rt + 3) * WPAD + k];
#pragma unroll
            for (int kk = 0; kk < 4; kk++) {
                float hv[4];
#pragma unroll
                for (int j = 0; j < 4; j++) hv[j] = h_sh[(k + kk) * HPAD + bt + j];
#pragma unroll
                for (int j = 0; j < 4; j++) {
                    C[0][j] += w0[kk] * hv[j];
                    C[1][j] += w1[kk] * hv[j];
                    C[2][j] += w2[kk] * hv[j];
                    C[3][j] += w3[kk] * hv[j];
                }
            }
        }
#pragma unroll
        for (int i = 0; i < 4; i++)
#pragma unroll
            for (int j = 0; j < 4; j++)
                zp[(ks * 32 + rt + i) * 33 + bt + j] = C[i][j];
        __syncthreads();

        // gate stage: thread (gb, gj) owns hidden unit j = jblock+gj for batch gb
        {
            float z[4];
#pragma unroll
            for (int g4 = 0; g4 < 4; g4++) {
                int r = g4 * 8 + gj;
                z[g4] = xwv[g4]
                      + zp[(0 * 32 + r) * 33 + gb] + zp[(1 * 32 + r) * 33 + gb]
                      + zp[(2 * 32 + r) * 33 + gb] + zp[(3 * 32 + r) * 33 + gb];
            }
            float ig = sigf(z[0]);
            float fg = sigf(z[1]);
            float gg = tanhfast(z[2]);
            float og = sigf(z[3]);
            float c = fg * c_sh[gj * 32 + gb] + ig * gg;
            float h = og * tanhfast(c);
            c_sh[gj * 32 + gb] = c;
            int j = jblock + gj;
            g_hbuf[(t + 1) & 1][dir][gb][j] = h;
            int tt = dir ? (Tt - 1 - t) : t;
            g_hall[dir][tt][gb][j] = h;
        }
        grid_barrier((unsigned)(t + 1) * NRNN_CTAS);
    }
}

// ---------------- K3: feats = concat(hf,hb) @ W_out^T + b_out ----------------
// grid 256 (per t), block 256. m-chunks of 128 through smem.
__global__ __launch_bounds__(256) void k_feats(const float* __restrict__ Wout,
                                               const float* __restrict__ bout) {
    __shared__ float x_sh[32][132];
    __shared__ float w_sh[32][132];
    const int tid = threadIdx.x;
    const int t = blockIdx.x;
    const int b = tid >> 3;
    const int kb = (tid & 7) << 2;

    float acc[4] = {0.0f, 0.0f, 0.0f, 0.0f};
    for (int c = 0; c < 2 * Hh; c += 128) {
        for (int i = tid; i < 32 * 128; i += 256) {
            int r = i >> 7, mm = i & 127;
            int mg = c + mm;
            x_sh[r][mm] = (mg < Hh) ? g_hall[0][t][r][mg] : g_hall[1][t][r][mg - Hh];
            w_sh[r][mm] = Wout[r * (2 * Hh) + mg];   // r is k-index here
        }
        __syncthreads();
        for (int mm = 0; mm < 128; mm += 4) {
            float xv[4];
            *(float4*)xv = *(const float4*)&x_sh[b][mm];
#pragma unroll
            for (int i = 0; i < 4; i++) {
                float wv[4];
                *(float4*)wv = *(const float4*)&w_sh[kb + i][mm];
                acc[i] += xv[0] * wv[0] + xv[1] * wv[1] + xv[2] * wv[2] + xv[3] * wv[3];
            }
        }
        __syncthreads();
    }
    float4 o;
    o.x = acc[0] + bout[kb + 0];
    o.y = acc[1] + bout[kb + 1];
    o.z = acc[2] + bout[kb + 2];
    o.w = acc[3] + bout[kb + 3];
    *(float4*)&g_feats[t][b][kb] = o;
}

// ---------------- K4: Viterbi forward + backtrack + output ----------------
// 32 CTAs (one per batch) x 32 threads (lane = tag).
__global__ __launch_bounds__(32) void k_vit(const float* __restrict__ trans,
                                            float* __restrict__ out) {
    __shared__ unsigned char bp_sh[Tt][Kk];
    const int b = blockIdx.x;
    const int lane = threadIdx.x;

    float tr[Kk];
#pragma unroll
    for (int p = 0; p < Kk; p++) tr[p] = trans[lane * Kk + p];   // trans[next=lane][prev=p]
    const float trstop = trans[31 * Kk + lane];                  // STOP = 31

    float v = (lane == 30) ? 0.0f : NEGV;                        // START = 30

    for (int t = 0; t < Tt; t++) {
        float best = -3.0e38f;
        int bp = 0;
#pragma unroll
        for (int p = 0; p < Kk; p++) {
            float vv = __shfl_sync(0xffffffffu, v, p);
            float s = vv + tr[p];
            if (s > best) { best = s; bp = p; }                  // strict > => first max (jnp.argmax)
        }
        float feat = g_feats[t][b][lane];
        v = best + feat;
        bp_sh[t][lane] = (unsigned char)bp;
    }

    float term = v + trstop;
    float bv = term;
    int bi = lane;
#pragma unroll
    for (int off = 16; off > 0; off >>= 1) {
        float ov = __shfl_down_sync(0xffffffffu, bv, off);
        int oi = __shfl_down_sync(0xffffffffu, bi, off);
        if (ov > bv || (ov == bv && oi < bi)) { bv = ov; bi = oi; }
    }
    __syncwarp();
    if (lane == 0) {
        out[b] = bv;                 // path_score
        int tag = bi;
        for (int t = Tt - 1; t >= 0; t--) {
            out[Bb + b * Tt + t] = (float)tag;
            tag = bp_sh[t][tag];
        }
    }
}

// ---------------- launch ----------------
extern "C" void kernel_launch(void* const* d_in, const int* in_sizes, int n_in,
                              void* d_out, int out_size) {
    (void)in_sizes; (void)n_in; (void)out_size;
    const int*   sent = (const int*)d_in[0];
    const float* emb  = (const float*)d_in[1];
    const float* Wihf = (const float*)d_in[2];
    const float* Whhf = (const float*)d_in[3];
    const float* bf   = (const float*)d_in[4];
    const float* Wihb = (const float*)d_in[5];
    const float* Whhb = (const float*)d_in[6];
    const float* bb   = (const float*)d_in[7];
    const float* Wout = (const float*)d_in[8];
    const float* bout = (const float*)d_in[9];
    const float* trn  = (const float*)d_in[10];
    const float* h0   = (const float*)d_in[11];
    const float* c0   = (const float*)d_in[12];
    float* out = (float*)d_out;

    const int smem_rnn = SM_RNN_FLOATS * 4;
    cudaFuncSetAttribute(k_rnn, cudaFuncAttributeMaxDynamicSharedMemorySize, smem_rnn);

    k_init<<<128, 256>>>(h0);
    dim3 g1(128, 32, 2);
    k_xw<<<g1, 256>>>(sent, emb, Wihf, bf, Wihb, bb);
    k_rnn<<<NRNN_CTAS, 256, smem_rnn>>>(Whhf, Whhb, c0);
    k_feats<<<Tt, 256>>>(Wout, bout);
    k_vit<<<Bb, 32>>>(trn, out);
}